// round 2
// baseline (speedup 1.0000x reference)
#include <cuda_runtime.h>

// Problem constants (match reference)
#define BOX   120
#define VOL   (BOX * BOX * BOX)       // 1,728,000
#define NTYPE 11
#define BATCH 4
#define BT    (BATCH * NTYPE)         // 44
#define MAXA  512
#define NNB   2                       // NUM_NEIGHBOURS
#define KDIM  5                       // 2*NNB+1
#define KTOT  (KDIM * KDIM * KDIM)    // 125

// ---------------------------------------------------------------------------
// num_atoms dtype sniff: values are in [1, 512]. If the buffer is int64
// (little-endian), 32-bit word 1 is the high half of element 0 == 0.
// If it is int32, word 1 is num_atoms[1] >= 1. So word1==0 <=> int64.
// ---------------------------------------------------------------------------
__device__ __forceinline__ int get_natoms(const int* __restrict__ p, int bt) {
    const bool is64 = (p[1] == 0);
    return is64 ? p[2 * bt] : p[bt];
}

// ---------------------------------------------------------------------------
// Kernel 1: zero the 304 MB output. Write-only, float4 stores, exact grid.
// ---------------------------------------------------------------------------
__global__ void __launch_bounds__(256) zero_kernel(float4* __restrict__ out, long long n4) {
    long long i = (long long)blockIdx.x * blockDim.x + threadIdx.x;
    if (i < n4) {
        out[i] = make_float4(0.f, 0.f, 0.f, 0.f);
    }
}

// ---------------------------------------------------------------------------
// Kernel 2: scatter gaussian density.
// One block (128 threads) per (bt, atom). Thread k in [0,125) handles one
// neighbor cell. atomicAdd result unused -> REDG (no return trip).
// ---------------------------------------------------------------------------
__global__ void __launch_bounds__(128) scatter_kernel(
    const float* __restrict__ coords,    // [BT, 3*MAXA]
    const int* __restrict__ num_atoms,   // [BT] int32 (or int64, sniffed)
    float* __restrict__ out)             // [BT, VOL]
{
    const int blk = blockIdx.x;
    const int bt = blk >> 9;        // / MAXA
    const int a  = blk & (MAXA - 1);
    if (a >= get_natoms(num_atoms, bt)) return;

    const int k = threadIdx.x;
    if (k >= KTOT) return;

    const float* p = coords + (long long)bt * (3 * MAXA) + 3 * a;
    const float x = p[0];
    const float y = p[1];
    const float z = p[2];

    const int cx = (int)floorf(x);
    const int cy = (int)floorf(y);
    const int cz = (int)floorf(z);

    const int ox = k / 25 - NNB;
    const int oy = (k / 5) % 5 - NNB;
    const int oz = k % 5 - NNB;

    const int ix = cx + ox;
    const int iy = cy + oy;
    const int iz = cz + oz;

    // Margin in the reference makes these almost always true; cheap predication.
    if ((unsigned)ix >= BOX || (unsigned)iy >= BOX || (unsigned)iz >= BOX) return;

    const float dx = (float)ix - x;
    const float dy = (float)iy - y;
    const float dz = (float)iz - z;
    const float v = __expf(-(dx * dx + dy * dy + dz * dz));

    atomicAdd(out + (long long)bt * VOL + (((long long)ix * BOX + iy) * BOX + iz), v);
}

// ---------------------------------------------------------------------------
extern "C" void kernel_launch(void* const* d_in, const int* in_sizes, int n_in,
                              void* d_out, int out_size) {
    const float* coords    = (const float*)d_in[0];  // float32 [4,11,1536]
    const int*   num_atoms = (const int*)d_in[1];    // int32/int64 [4,11]
    float*       out       = (float*)d_out;          // float32 [4,11,120,120,120]

    // out_size = 76,032,000 floats, divisible by 4.
    const long long n4 = (long long)out_size / 4;
    const int zblocks = (int)((n4 + 255) / 256);
    zero_kernel<<<zblocks, 256>>>((float4*)d_out, n4);

    scatter_kernel<<<BT * MAXA, 128>>>(coords, num_atoms, out);
}